// round 2
// baseline (speedup 1.0000x reference)
#include <cuda_runtime.h>
#include <math.h>

#define Nn 50000
#define Ee 250000
#define Bb 128
#define Dd 302
#define Qq 600
#define Cc 2000
#define NEG_SLOPE 0.2f

// ---------------- scratch (device globals; no allocation allowed) ----------
__device__ float g_h[(size_t)Nn * Dd];    // transformed features per layer
__device__ float g_o[(size_t)Nn * Dd];    // aggregated layer output
__device__ float g_as[Nn];
__device__ float g_ad[Nn];
__device__ float g_s[Nn];
__device__ int   g_cnt[Nn];
__device__ int   g_cur[Nn];
__device__ int   g_rowptr[Nn + 1];
__device__ int   g_csrc[Ee + Nn];
__device__ float g_qp[Bb * Dd];
__device__ float g_pool[Bb * Dd];

// ---------------- helpers ---------------------------------------------------
__device__ __forceinline__ float lrelu(float x) { return x > 0.f ? x : NEG_SLOPE * x; }

__device__ __forceinline__ int lower_bound_i(const int* a, int n, int v) {
    int lo = 0, hi = n;
    while (lo < hi) { int m = (lo + hi) >> 1; if (a[m] < v) lo = m + 1; else hi = m; }
    return lo;
}

// ---------------- CSR build --------------------------------------------------
__global__ void zero_k() {
    int i = blockIdx.x * blockDim.x + threadIdx.x;
    if (i < Nn) { g_cnt[i] = 0; g_cur[i] = 0; }
}

__global__ void count_k(const int* __restrict__ edges) {
    int i = blockIdx.x * blockDim.x + threadIdx.x;
    if (i >= Ee + Nn) return;
    int dst = (i < Ee) ? edges[Ee + i] : (i - Ee);
    atomicAdd(&g_cnt[dst], 1);
}

__global__ void scan_k() {
    __shared__ int sh[1024];
    __shared__ int carry_sh;
    int tid = threadIdx.x;
    if (tid == 0) carry_sh = 0;
    __syncthreads();
    for (int base = 0; base < Nn; base += 1024) {
        int i = base + tid;
        int v = (i < Nn) ? g_cnt[i] : 0;
        sh[tid] = v;
        __syncthreads();
        // Hillis-Steele inclusive scan
        #pragma unroll
        for (int off = 1; off < 1024; off <<= 1) {
            int t = (tid >= off) ? sh[tid - off] : 0;
            __syncthreads();
            sh[tid] += t;
            __syncthreads();
        }
        int incl = sh[tid];
        int carry = carry_sh;
        if (i < Nn) g_rowptr[i] = carry + incl - v;
        __syncthreads();
        if (tid == 1023) carry_sh = carry + incl;
        __syncthreads();
    }
    if (tid == 0) g_rowptr[Nn] = carry_sh;
}

__global__ void fill_k(const int* __restrict__ edges) {
    int i = blockIdx.x * blockDim.x + threadIdx.x;
    if (i >= Ee + Nn) return;
    int src, dst;
    if (i < Ee) { src = edges[i]; dst = edges[Ee + i]; }
    else        { src = dst = i - Ee; }
    int p = g_rowptr[dst] + atomicAdd(&g_cur[dst], 1);
    g_csrc[p] = src;
}

// ---------------- GEMM: C[M,Ncols] = A[M,K] * W[Ncols,K]^T ------------------
#define BM 128
#define BN 64
#define BK 16
__global__ __launch_bounds__(256) void gemm_nt(const float* __restrict__ A,
                                               const float* __restrict__ W,
                                               float* __restrict__ C,
                                               int M, int Ncols, int K) {
    __shared__ float As[BK][BM + 1];
    __shared__ float Ws[BK][BN + 1];
    int tid = threadIdx.x;
    int m0 = blockIdx.y * BM, n0 = blockIdx.x * BN;
    int ty = tid >> 4, tx = tid & 15;
    float acc[8][4];
    #pragma unroll
    for (int i = 0; i < 8; i++)
        #pragma unroll
        for (int j = 0; j < 4; j++) acc[i][j] = 0.f;

    for (int k0 = 0; k0 < K; k0 += BK) {
        #pragma unroll
        for (int e = 0; e < 8; e++) {
            int idx = tid + e * 256;
            int r = idx >> 4, c = idx & 15;
            int gm = m0 + r, gk = k0 + c;
            As[c][r] = (gm < M && gk < K) ? A[(size_t)gm * K + gk] : 0.f;
        }
        #pragma unroll
        for (int e = 0; e < 4; e++) {
            int idx = tid + e * 256;
            int r = idx >> 4, c = idx & 15;
            int gn = n0 + r, gk = k0 + c;
            Ws[c][r] = (gn < Ncols && gk < K) ? W[(size_t)gn * K + gk] : 0.f;
        }
        __syncthreads();
        #pragma unroll
        for (int k = 0; k < BK; k++) {
            float a[8], b[4];
            #pragma unroll
            for (int i = 0; i < 8; i++) a[i] = As[k][ty * 8 + i];
            #pragma unroll
            for (int j = 0; j < 4; j++) b[j] = Ws[k][tx * 4 + j];
            #pragma unroll
            for (int i = 0; i < 8; i++)
                #pragma unroll
                for (int j = 0; j < 4; j++) acc[i][j] += a[i] * b[j];
        }
        __syncthreads();
    }
    #pragma unroll
    for (int i = 0; i < 8; i++) {
        int gm = m0 + ty * 8 + i;
        if (gm >= M) continue;
        #pragma unroll
        for (int j = 0; j < 4; j++) {
            int gn = n0 + tx * 4 + j;
            if (gn < Ncols) C[(size_t)gm * Ncols + gn] = acc[i][j];
        }
    }
}

// ---------------- attention scalar dots: a_s, a_d ---------------------------
__global__ void attdots_k(const float* __restrict__ h,
                          const float* __restrict__ att_s,
                          const float* __restrict__ att_d) {
    int w = (blockIdx.x * blockDim.x + threadIdx.x) >> 5;
    int lane = threadIdx.x & 31;
    if (w >= Nn) return;
    const float* hr = h + (size_t)w * Dd;
    float s = 0.f, d = 0.f;
    for (int c = lane; c < Dd; c += 32) {
        float v = hr[c];
        s += v * att_s[c];
        d += v * att_d[c];
    }
    #pragma unroll
    for (int o = 16; o; o >>= 1) {
        s += __shfl_xor_sync(0xffffffffu, s, o);
        d += __shfl_xor_sync(0xffffffffu, d, o);
    }
    if (lane == 0) { g_as[w] = s; g_ad[w] = d; }
}

// ---------------- fused edge softmax + aggregation (warp per dst) -----------
__global__ void agg_k(const float* __restrict__ h,
                      const float* __restrict__ bias,
                      float* __restrict__ out) {
    int w = (blockIdx.x * blockDim.x + threadIdx.x) >> 5;
    int lane = threadIdx.x & 31;
    if (w >= Nn) return;
    int beg = g_rowptr[w], end = g_rowptr[w + 1];
    float ad = g_ad[w];

    float m = -3.4e38f;
    for (int j = beg + lane; j < end; j += 32)
        m = fmaxf(m, lrelu(g_as[g_csrc[j]] + ad));
    #pragma unroll
    for (int o = 16; o; o >>= 1) m = fmaxf(m, __shfl_xor_sync(0xffffffffu, m, o));

    float den = 0.f;
    for (int j = beg + lane; j < end; j += 32)
        den += expf(lrelu(g_as[g_csrc[j]] + ad) - m);
    #pragma unroll
    for (int o = 16; o; o >>= 1) den += __shfl_xor_sync(0xffffffffu, den, o);
    float inv = 1.f / den;

    float acc[10];
    #pragma unroll
    for (int i = 0; i < 10; i++) acc[i] = 0.f;

    for (int j = beg; j < end; j++) {
        int s = g_csrc[j];
        float wgt = expf(lrelu(g_as[s] + ad) - m) * inv;
        const float* hr = h + (size_t)s * Dd;
        #pragma unroll
        for (int i = 0; i < 9; i++) acc[i] += wgt * hr[lane + i * 32];
        int c = lane + 288;
        if (c < Dd) acc[9] += wgt * hr[c];
    }
    #pragma unroll
    for (int i = 0; i < 10; i++) {
        int c = lane + i * 32;
        if (c < Dd) {
            float v = acc[i] + bias[c];
            out[(size_t)w * Dd + c] = v > 0.f ? v : 0.f;  // ReLU fused
        }
    }
}

// ---------------- qp = query @ attW  [B,D] ----------------------------------
__global__ void qp_k(const float* __restrict__ query, const float* __restrict__ attW) {
    int b = blockIdx.x;
    __shared__ float q[Qq];
    for (int i = threadIdx.x; i < Qq; i += blockDim.x) q[i] = query[(size_t)b * Qq + i];
    __syncthreads();
    for (int d = threadIdx.x; d < Dd; d += blockDim.x) {
        float acc = 0.f;
        for (int qi = 0; qi < Qq; qi++) acc += q[qi] * attW[(size_t)qi * Dd + d];
        g_qp[b * Dd + d] = acc;
    }
}

// ---------------- per-node score s[n] ---------------------------------------
__global__ void score_k(const float* __restrict__ h, const int* __restrict__ batch) {
    int w = (blockIdx.x * blockDim.x + threadIdx.x) >> 5;
    int lane = threadIdx.x & 31;
    if (w >= Nn) return;
    int b = batch[w];
    const float* qr = g_qp + b * Dd;
    const float* hr = h + (size_t)w * Dd;
    float s = 0.f;
    for (int c = lane; c < Dd; c += 32) s += qr[c] * hr[c];
    #pragma unroll
    for (int o = 16; o; o >>= 1) s += __shfl_xor_sync(0xffffffffu, s, o);
    if (lane == 0) g_s[w] = s * 0.04082482904638630f;  // 1/sqrt(600)
}

// ---------------- block-per-graph softmax pooling (batch is sorted) ---------
__global__ __launch_bounds__(512) void pool_k(const float* __restrict__ h,
                                              const int* __restrict__ batch) {
    int b = blockIdx.x;
    int tid = threadIdx.x;
    __shared__ float red[512];
    int start = lower_bound_i(batch, Nn, b);
    int end   = lower_bound_i(batch, Nn, b + 1);

    float m = -3.4e38f;
    for (int n = start + tid; n < end; n += 512) m = fmaxf(m, g_s[n]);
    red[tid] = m; __syncthreads();
    for (int o = 256; o; o >>= 1) { if (tid < o) red[tid] = fmaxf(red[tid], red[tid + o]); __syncthreads(); }
    m = red[0]; __syncthreads();

    float ds = 0.f;
    for (int n = start + tid; n < end; n += 512) ds += expf(g_s[n] - m);
    red[tid] = ds; __syncthreads();
    for (int o = 256; o; o >>= 1) { if (tid < o) red[tid] += red[tid + o]; __syncthreads(); }
    float total = red[0];
    float inv = (total > 0.f) ? 1.f / total : 0.f;
    __syncthreads();

    float acc = 0.f;
    for (int t = start; t < end; t += 512) {
        int j = t + tid;
        red[tid] = (j < end) ? expf(g_s[j] - m) * inv : 0.f;
        __syncthreads();
        int cnt = min(512, end - t);
        if (tid < Dd) {
            for (int u = 0; u < cnt; u++)
                acc += red[u] * h[(size_t)(t + u) * Dd + tid];
        }
        __syncthreads();
    }
    if (tid < Dd) g_pool[b * Dd + tid] = acc > 0.f ? acc : 0.f;  // ReLU fused
}

// ---------------- final: out = relu(pooled) @ lin_w^T + lin_b ---------------
__global__ void final_k(const float* __restrict__ lin_w,
                        const float* __restrict__ lin_b,
                        float* __restrict__ out) {
    int b = blockIdx.x;
    __shared__ float p[Dd];
    for (int i = threadIdx.x; i < Dd; i += blockDim.x) p[i] = g_pool[b * Dd + i];
    __syncthreads();
    int warp = threadIdx.x >> 5, lane = threadIdx.x & 31;
    for (int c = warp; c < Cc; c += 8) {
        const float* wr = lin_w + (size_t)c * Dd;
        float a = 0.f;
        for (int k = lane; k < Dd; k += 32) a += p[k] * wr[k];
        #pragma unroll
        for (int o = 16; o; o >>= 1) a += __shfl_xor_sync(0xffffffffu, a, o);
        if (lane == 0) out[(size_t)b * Cc + c] = a + lin_b[c];
    }
}

// ---------------- launch -----------------------------------------------------
extern "C" void kernel_launch(void* const* d_in, const int* in_sizes, int n_in,
                              void* d_out, int out_size) {
    const float* x        = (const float*)d_in[0];
    const int*   edges    = (const int*)  d_in[1];
    const float* query    = (const float*)d_in[2];
    const int*   batch    = (const int*)  d_in[3];
    const float* theta    = (const float*)d_in[4];
    const float* att_src  = (const float*)d_in[5];
    const float* att_dst  = (const float*)d_in[6];
    const float* gat_bias = (const float*)d_in[7];
    const float* attW     = (const float*)d_in[8];
    const float* lin_w    = (const float*)d_in[9];
    const float* lin_b    = (const float*)d_in[10];
    float* out = (float*)d_out;

    float *p_h, *p_o;
    cudaGetSymbolAddress((void**)&p_h, g_h);
    cudaGetSymbolAddress((void**)&p_o, g_o);

    // CSR build (graph is fixed within a launch; must be rebuilt each call)
    zero_k<<<(Nn + 255) / 256, 256>>>();
    count_k<<<(Ee + Nn + 255) / 256, 256>>>(edges);
    scan_k<<<1, 1024>>>();
    fill_k<<<(Ee + Nn + 255) / 256, 256>>>(edges);

    dim3 ggrid((Dd + BN - 1) / BN, (Nn + BM - 1) / BM);
    int wgrid = (Nn * 32 + 255) / 256;

    const float* in = x;
    for (int l = 0; l < 3; l++) {
        gemm_nt<<<ggrid, 256>>>(in, theta, p_h, Nn, Dd, Dd);
        attdots_k<<<wgrid, 256>>>(p_h, att_src, att_dst);
        agg_k<<<wgrid, 256>>>(p_h, gat_bias, p_o);
        in = p_o;
    }

    qp_k<<<Bb, 384>>>(query, attW);
    score_k<<<wgrid, 256>>>(p_o, batch);
    pool_k<<<Bb, 512>>>(p_o, batch);
    final_k<<<Bb, 256>>>(lin_w, lin_b, out);
}

// round 4
// speedup vs baseline: 1.4907x; 1.4907x over previous
#include <cuda_runtime.h>
#include <math.h>
#include <stdint.h>

#define Nn 50000
#define Ee 250000
#define Bb 128
#define Dd 302
#define Qq 600
#define Cc 2000
#define NEG_SLOPE 0.2f

// ---------------- scratch (device globals; no allocation allowed) ----------
__device__ float g_h[(size_t)Nn * Dd];
__device__ float g_o[(size_t)Nn * Dd];
__device__ float g_as[Nn];
__device__ float g_ad[Nn];
__device__ float g_s[Nn];
__device__ int   g_cnt[Nn];
__device__ int   g_cur[Nn];
__device__ int   g_rowptr[Nn + 1];
__device__ int   g_csrc[Ee + Nn];
__device__ float g_qp[Bb * Dd];
__device__ float g_pool[Bb * Dd];

// ---------------- helpers ---------------------------------------------------
__device__ __forceinline__ float lrelu(float x) { return x > 0.f ? x : NEG_SLOPE * x; }

__device__ __forceinline__ int lower_bound_i(const int* a, int n, int v) {
    int lo = 0, hi = n;
    while (lo < hi) { int m = (lo + hi) >> 1; if (a[m] < v) lo = m + 1; else hi = m; }
    return lo;
}

__device__ __forceinline__ float tf32f(float f) {
    uint32_t r; asm("cvt.rna.tf32.f32 %0, %1;" : "=r"(r) : "f"(f));
    return __uint_as_float(r);
}

#define MMA_TF32(cr, a, b) \
    asm volatile("mma.sync.aligned.m16n8k8.row.col.f32.tf32.tf32.f32 " \
        "{%0,%1,%2,%3}, {%4,%5,%6,%7}, {%8,%9}, {%0,%1,%2,%3};" \
        : "+f"((cr)[0]), "+f"((cr)[1]), "+f"((cr)[2]), "+f"((cr)[3]) \
        : "r"((a)[0]), "r"((a)[1]), "r"((a)[2]), "r"((a)[3]), \
          "r"((b)[0]), "r"((b)[1]))

// ---------------- CSR build --------------------------------------------------
__global__ void zero_k() {
    int i = blockIdx.x * blockDim.x + threadIdx.x;
    if (i < Nn) { g_cnt[i] = 0; g_cur[i] = 0; }
}

__global__ void count_k(const int* __restrict__ edges) {
    int i = blockIdx.x * blockDim.x + threadIdx.x;
    if (i >= Ee + Nn) return;
    int dst = (i < Ee) ? edges[Ee + i] : (i - Ee);
    atomicAdd(&g_cnt[dst], 1);
}

__global__ void scan_k() {
    __shared__ int sh[1024];
    __shared__ int carry_sh;
    int tid = threadIdx.x;
    if (tid == 0) carry_sh = 0;
    __syncthreads();
    for (int base = 0; base < Nn; base += 1024) {
        int i = base + tid;
        int v = (i < Nn) ? g_cnt[i] : 0;
        sh[tid] = v;
        __syncthreads();
        #pragma unroll
        for (int off = 1; off < 1024; off <<= 1) {
            int t = (tid >= off) ? sh[tid - off] : 0;
            __syncthreads();
            sh[tid] += t;
            __syncthreads();
        }
        int incl = sh[tid];
        int carry = carry_sh;
        if (i < Nn) g_rowptr[i] = carry + incl - v;
        __syncthreads();
        if (tid == 1023) carry_sh = carry + incl;
        __syncthreads();
    }
    if (tid == 0) g_rowptr[Nn] = carry_sh;
}

__global__ void fill_k(const int* __restrict__ edges) {
    int i = blockIdx.x * blockDim.x + threadIdx.x;
    if (i >= Ee + Nn) return;
    int src, dst;
    if (i < Ee) { src = edges[i]; dst = edges[Ee + i]; }
    else        { src = dst = i - Ee; }
    int p = g_rowptr[dst] + atomicAdd(&g_cur[dst], 1);
    g_csrc[p] = src;
}

// ---------------- tf32 mma.sync GEMM: C[M,302] = A[M,302] @ W[302,302]^T ----
// CTA tile 128x128x16. 8 warps as 2(m) x 4(n); warp tile 64x32.
// 3-term tf32 split (hi*hi + hi*lo + lo*hi) for ~fp32 accuracy.
#define BMt 128
#define BNt 128
#define BKt 16
#define SWd 20   // padded shared row width (16 k-values + 4 pad) -> conflict-free frags

__global__ __launch_bounds__(256, 2) void gemm_mma_k(const float* __restrict__ A,
                                                     const float* __restrict__ W,
                                                     float* __restrict__ C) {
    __shared__ float As_hi[BMt][SWd], As_lo[BMt][SWd];
    __shared__ float Ws_hi[BNt][SWd], Ws_lo[BNt][SWd];

    int tid = threadIdx.x;
    int wid = tid >> 5, lane = tid & 31;
    int g = lane >> 2, t = lane & 3;
    int m0 = blockIdx.y * BMt, n0 = blockIdx.x * BNt;
    int wm = (wid >> 2) * 64;      // 0 or 64
    int wn = (wid & 3) * 32;       // 0,32,64,96

    float c[4][4][4];
    #pragma unroll
    for (int i = 0; i < 4; i++)
        #pragma unroll
        for (int j = 0; j < 4; j++)
            #pragma unroll
            for (int f = 0; f < 4; f++) c[i][j][f] = 0.f;

    int srow = tid >> 3;   // 0..31
    int sk2  = tid & 7;    // float2 index within 16-wide k

    for (int k0 = 0; k0 < Dd; k0 += BKt) {
        __syncthreads();   // previous iter's fragment reads done before overwrite
        // stage A [128 x 16] -> hi/lo tf32
        #pragma unroll
        for (int e = 0; e < 4; e++) {
            int m = srow + e * 32;
            int gm = m0 + m, gk = k0 + 2 * sk2;
            float2 v = make_float2(0.f, 0.f);
            if (gm < Nn && gk < Dd) v = *(const float2*)(A + (size_t)gm * Dd + gk);
            float hx = tf32f(v.x), hy = tf32f(v.y);
            *(float2*)&As_hi[m][2 * sk2] = make_float2(hx, hy);
            *(float2*)&As_lo[m][2 * sk2] = make_float2(tf32f(v.x - hx), tf32f(v.y - hy));
        }
        // stage W [128 x 16] -> hi/lo tf32
        #pragma unroll
        for (int e = 0; e < 4; e++) {
            int n = srow + e * 32;
            int gn = n0 + n, gk = k0 + 2 * sk2;
            float2 v = make_float2(0.f, 0.f);
            if (gn < Dd && gk < Dd) v = *(const float2*)(W + (size_t)gn * Dd + gk);
            float hx = tf32f(v.x), hy = tf32f(v.y);
            *(float2*)&Ws_hi[n][2 * sk2] = make_float2(hx, hy);
            *(float2*)&Ws_lo[n][2 * sk2] = make_float2(tf32f(v.x - hx), tf32f(v.y - hy));
        }
        __syncthreads();

        #pragma unroll
        for (int kk = 0; kk < 2; kk++) {
            int kb = kk * 8;
            uint32_t bh[4][2], bl[4][2];
            #pragma unroll
            for (int nt = 0; nt < 4; nt++) {
                int nr = wn + nt * 8 + g;
                bh[nt][0] = __float_as_uint(Ws_hi[nr][kb + t]);
                bh[nt][1] = __float_as_uint(Ws_hi[nr][kb + t + 4]);
                bl[nt][0] = __float_as_uint(Ws_lo[nr][kb + t]);
                bl[nt][1] = __float_as_uint(Ws_lo[nr][kb + t + 4]);
            }
            #pragma unroll
            for (int mt = 0; mt < 4; mt++) {
                int mr = wm + mt * 16 + g;
                uint32_t ah[4], al[4];
                ah[0] = __float_as_uint(As_hi[mr][kb + t]);
                ah[1] = __float_as_uint(As_hi[mr + 8][kb + t]);
                ah[2] = __float_as_uint(As_hi[mr][kb + t + 4]);
                ah[3] = __float_as_uint(As_hi[mr + 8][kb + t + 4]);
                al[0] = __float_as_uint(As_lo[mr][kb + t]);
                al[1] = __float_as_uint(As_lo[mr + 8][kb + t]);
                al[2] = __float_as_uint(As_lo[mr][kb + t + 4]);
                al[3] = __float_as_uint(As_lo[mr + 8][kb + t + 4]);
                #pragma unroll
                for (int nt = 0; nt < 4; nt++) {
                    MMA_TF32(c[mt][nt], ah, bh[nt]);
                    MMA_TF32(c[mt][nt], ah, bl[nt]);
                    MMA_TF32(c[mt][nt], al, bh[nt]);
                }
            }
        }
    }

    // epilogue: c0,c1 -> (row, col..col+1); c2,c3 -> (row+8, col..col+1)
    #pragma unroll
    for (int mt = 0; mt < 4; mt++) {
        int row = m0 + wm + mt * 16 + g;
        #pragma unroll
        for (int nt = 0; nt < 4; nt++) {
            int col = n0 + wn + nt * 8 + 2 * t;
            if (col < Dd) {
                if (row < Nn)
                    *(float2*)(C + (size_t)row * Dd + col) =
                        make_float2(c[mt][nt][0], c[mt][nt][1]);
                if (row + 8 < Nn)
                    *(float2*)(C + (size_t)(row + 8) * Dd + col) =
                        make_float2(c[mt][nt][2], c[mt][nt][3]);
            }
        }
    }
}

// ---------------- attention scalar dots: a_s, a_d ---------------------------
__global__ void attdots_k(const float* __restrict__ h,
                          const float* __restrict__ att_s,
                          const float* __restrict__ att_d) {
    int w = (blockIdx.x * blockDim.x + threadIdx.x) >> 5;
    int lane = threadIdx.x & 31;
    if (w >= Nn) return;
    const float* hr = h + (size_t)w * Dd;
    float s = 0.f, d = 0.f;
    for (int c = lane; c < Dd; c += 32) {
        float v = hr[c];
        s += v * att_s[c];
        d += v * att_d[c];
    }
    #pragma unroll
    for (int o = 16; o; o >>= 1) {
        s += __shfl_xor_sync(0xffffffffu, s, o);
        d += __shfl_xor_sync(0xffffffffu, d, o);
    }
    if (lane == 0) { g_as[w] = s; g_ad[w] = d; }
}

// ---------------- fused edge softmax + aggregation (warp per dst) -----------
__global__ void agg_k(const float* __restrict__ h,
                      const float* __restrict__ bias,
                      float* __restrict__ out) {
    int w = (blockIdx.x * blockDim.x + threadIdx.x) >> 5;
    int lane = threadIdx.x & 31;
    if (w >= Nn) return;
    int beg = g_rowptr[w], end = g_rowptr[w + 1];
    float ad = g_ad[w];

    float m = -3.4e38f;
    for (int j = beg + lane; j < end; j += 32)
        m = fmaxf(m, lrelu(g_as[g_csrc[j]] + ad));
    #pragma unroll
    for (int o = 16; o; o >>= 1) m = fmaxf(m, __shfl_xor_sync(0xffffffffu, m, o));

    float den = 0.f;
    for (int j = beg + lane; j < end; j += 32)
        den += expf(lrelu(g_as[g_csrc[j]] + ad) - m);
    #pragma unroll
    for (int o = 16; o; o >>= 1) den += __shfl_xor_sync(0xffffffffu, den, o);
    float inv = 1.f / den;

    float acc[10];
    #pragma unroll
    for (int i = 0; i < 10; i++) acc[i] = 0.f;

    for (int j = beg; j < end; j++) {
        int s = g_csrc[j];
        float wgt = expf(lrelu(g_as[s] + ad) - m) * inv;
        const float* hr = h + (size_t)s * Dd;
        #pragma unroll
        for (int i = 0; i < 9; i++) acc[i] += wgt * hr[lane + i * 32];
        int c = lane + 288;
        if (c < Dd) acc[9] += wgt * hr[c];
    }
    #pragma unroll
    for (int i = 0; i < 10; i++) {
        int c = lane + i * 32;
        if (c < Dd) {
            float v = acc[i] + bias[c];
            out[(size_t)w * Dd + c] = v > 0.f ? v : 0.f;  // ReLU fused
        }
    }
}

// ---------------- qp = query @ attW  [B,D] ----------------------------------
__global__ void qp_k(const float* __restrict__ query, const float* __restrict__ attW) {
    int b = blockIdx.x;
    __shared__ float q[Qq];
    for (int i = threadIdx.x; i < Qq; i += blockDim.x) q[i] = query[(size_t)b * Qq + i];
    __syncthreads();
    for (int d = threadIdx.x; d < Dd; d += blockDim.x) {
        float acc = 0.f;
        for (int qi = 0; qi < Qq; qi++) acc += q[qi] * attW[(size_t)qi * Dd + d];
        g_qp[b * Dd + d] = acc;
    }
}

// ---------------- per-node score s[n] ---------------------------------------
__global__ void score_k(const float* __restrict__ h, const int* __restrict__ batch) {
    int w = (blockIdx.x * blockDim.x + threadIdx.x) >> 5;
    int lane = threadIdx.x & 31;
    if (w >= Nn) return;
    int b = batch[w];
    const float* qr = g_qp + b * Dd;
    const float* hr = h + (size_t)w * Dd;
    float s = 0.f;
    for (int c = lane; c < Dd; c += 32) s += qr[c] * hr[c];
    #pragma unroll
    for (int o = 16; o; o >>= 1) s += __shfl_xor_sync(0xffffffffu, s, o);
    if (lane == 0) g_s[w] = s * 0.04082482904638630f;  // 1/sqrt(600)
}

// ---------------- block-per-graph softmax pooling (batch is sorted) ---------
__global__ __launch_bounds__(512) void pool_k(const float* __restrict__ h,
                                              const int* __restrict__ batch) {
    int b = blockIdx.x;
    int tid = threadIdx.x;
    __shared__ float red[512];
    int start = lower_bound_i(batch, Nn, b);
    int end   = lower_bound_i(batch, Nn, b + 1);

    float m = -3.4e38f;
    for (int n = start + tid; n < end; n += 512) m = fmaxf(m, g_s[n]);
    red[tid] = m; __syncthreads();
    for (int o = 256; o; o >>= 1) { if (tid < o) red[tid] = fmaxf(red[tid], red[tid + o]); __syncthreads(); }
    m = red[0]; __syncthreads();

    float ds = 0.f;
    for (int n = start + tid; n < end; n += 512) ds += expf(g_s[n] - m);
    red[tid] = ds; __syncthreads();
    for (int o = 256; o; o >>= 1) { if (tid < o) red[tid] += red[tid + o]; __syncthreads(); }
    float total = red[0];
    float inv = (total > 0.f) ? 1.f / total : 0.f;
    __syncthreads();

    float acc = 0.f;
    for (int t = start; t < end; t += 512) {
        int j = t + tid;
        red[tid] = (j < end) ? expf(g_s[j] - m) * inv : 0.f;
        __syncthreads();
        int cnt = min(512, end - t);
        if (tid < Dd) {
            for (int u = 0; u < cnt; u++)
                acc += red[u] * h[(size_t)(t + u) * Dd + tid];
        }
        __syncthreads();
    }
    if (tid < Dd) g_pool[b * Dd + tid] = acc > 0.f ? acc : 0.f;  // ReLU fused
}

// ---------------- final: out = relu(pooled) @ lin_w^T + lin_b ---------------
__global__ void final_k(const float* __restrict__ lin_w,
                        const float* __restrict__ lin_b,
                        float* __restrict__ out) {
    int b = blockIdx.x;
    __shared__ float p[Dd];
    for (int i = threadIdx.x; i < Dd; i += blockDim.x) p[i] = g_pool[b * Dd + i];
    __syncthreads();
    int warp = threadIdx.x >> 5, lane = threadIdx.x & 31;
    for (int c = warp; c < Cc; c += 8) {
        const float* wr = lin_w + (size_t)c * Dd;
        float a = 0.f;
        for (int k = lane; k < Dd; k += 32) a += p[k] * wr[k];
        #pragma unroll
        for (int o = 16; o; o >>= 1) a += __shfl_xor_sync(0xffffffffu, a, o);
        if (lane == 0) out[(size_t)b * Cc + c] = a + lin_b[c];
    }
}

// ---------------- launch -----------------------------------------------------
extern "C" void kernel_launch(void* const* d_in, const int* in_sizes, int n_in,
                              void* d_out, int out_size) {
    const float* x        = (const float*)d_in[0];
    const int*   edges    = (const int*)  d_in[1];
    const float* query    = (const float*)d_in[2];
    const int*   batch    = (const int*)  d_in[3];
    const float* theta    = (const float*)d_in[4];
    const float* att_src  = (const float*)d_in[5];
    const float* att_dst  = (const float*)d_in[6];
    const float* gat_bias = (const float*)d_in[7];
    const float* attW     = (const float*)d_in[8];
    const float* lin_w    = (const float*)d_in[9];
    const float* lin_b    = (const float*)d_in[10];
    float* out = (float*)d_out;

    float *p_h, *p_o;
    cudaGetSymbolAddress((void**)&p_h, g_h);
    cudaGetSymbolAddress((void**)&p_o, g_o);

    // CSR build
    zero_k<<<(Nn + 255) / 256, 256>>>();
    count_k<<<(Ee + Nn + 255) / 256, 256>>>(edges);
    scan_k<<<1, 1024>>>();
    fill_k<<<(Ee + Nn + 255) / 256, 256>>>(edges);

    dim3 ggrid((Dd + BNt - 1) / BNt, (Nn + BMt - 1) / BMt);
    int wgrid = (Nn * 32 + 255) / 256;

    const float* in = x;
    for (int l = 0; l < 3; l++) {
        gemm_mma_k<<<ggrid, 256>>>(in, theta, p_h);
        attdots_k<<<wgrid, 256>>>(p_h, att_src, att_dst);
        agg_k<<<wgrid, 256>>>(p_h, gat_bias, p_o);
        in = p_o;
    }

    qp_k<<<Bb, 384>>>(query, attW);
    score_k<<<wgrid, 256>>>(p_o, batch);
    pool_k<<<Bb, 512>>>(p_o, batch);
    final_k<<<Bb, 256>>>(lin_w, lin_b, out);
}